// round 13
// baseline (speedup 1.0000x reference)
#include <cuda_runtime.h>
#include <cstdint>

#define N_ETA 7
#define FDIM 68
#define HW (512*1024)
#define CHUNK 512
#define NCH (HW / CHUNK)          // 1024
#define SLOTS 544                 // 512 + up to 21 pad slots <= 533; padded to 544
#define THREADS 544               // 17 warps == worst-case slice count
#define WROW 80                   // per-f row: 4 teams * 20 (17 used + 3 pad)
#define WSTRIDE (FDIM*WROW + 4)   // 5444 floats; %4==0 keeps 16B align, +4 skews banks
#define TBUFW (17*SLOTS)          // 9248 floats per buffer

__device__ uint16_t g_sorted[NCH * SLOTS];
__device__ int g_nsl[NCH];

// ---------------- threefry2x32, key (0,42), jax partitionable path ----------------
__device__ __forceinline__ void threefry2x32_k42(uint32_t& x0, uint32_t& x1) {
    const uint32_t K2 = 0x1BD11BDAu ^ 0u ^ 42u;
#define TFR(r) { x0 += x1; x1 = __funnelshift_l(x1, x1, (r)); x1 ^= x0; }
    x1 += 42u;
    TFR(13) TFR(15) TFR(26) TFR(6)
    x0 += 42u;  x1 += K2 + 1u;
    TFR(17) TFR(29) TFR(16) TFR(24)
    x0 += K2;   x1 += 0u + 2u;
    TFR(13) TFR(15) TFR(26) TFR(6)
    x1 += 42u + 3u;
    TFR(17) TFR(29) TFR(16) TFR(24)
    x0 += 42u;  x1 += K2 + 4u;
    TFR(13) TFR(15) TFR(26) TFR(6)
    x0 += K2;   x1 += 0u + 5u;
#undef TFR
}

__device__ __forceinline__ float gumbel_from_bits(uint32_t bits) {
    float f = __uint_as_float((bits >> 9) | 0x3F800000u) - 1.0f;
    const float tiny = 1.1754943508222875e-38f;
    float u = fmaxf(tiny, f + tiny);
    return -logf(-logf(u));
}

// eta + chunk-local expert sort into groups PADDED TO 4.
// entry: bits[0:9)=local px, [9:12)=expert, [12]=valid.
__global__ __launch_bounds__(CHUNK)
void eta_sort_kernel(const float* __restrict__ T, const int* __restrict__ eta) {
    __shared__ float logT[N_ETA * N_ETA];
    __shared__ uint16_t ent[SLOTS];
    __shared__ int hist[N_ETA], start[N_ETA + 1], cur[N_ETA];

    const int tid = threadIdx.x;
    const int c = blockIdx.x;
    const int cb = c * CHUNK;

    if (tid < N_ETA * N_ETA) logT[tid] = logf(T[tid] + 1e-9f);
    if (tid < N_ETA) hist[tid] = 0;
    for (int s = tid; s < SLOTS; s += CHUNK) ent[s] = 0;
    __syncthreads();

    int myE = 0;
    {
        int p = cb + tid;
        int r = eta[p] * N_ETA;
        float best = -3.0e38f;
#pragma unroll
        for (int k = 0; k < N_ETA; k++) {
            uint32_t x0 = 0u;
            uint32_t x1 = (uint32_t)(p * 7 + k);
            threefry2x32_k42(x0, x1);
            float v = logT[r + k] + gumbel_from_bits(x0 ^ x1);
            if (v > best) { best = v; myE = k; }
        }
        atomicAdd(&hist[myE], 1);
    }
    __syncthreads();
    if (tid == 0) {
        int s = 0;
        for (int e = 0; e < N_ETA; e++) { start[e] = s; cur[e] = s; s += (hist[e] + 3) & ~3; }
        start[N_ETA] = s;                 // <= 533
        g_nsl[c] = (s + 31) >> 5;         // <= 17
    }
    __syncthreads();
    {
        int pos = atomicAdd(&cur[myE], 1);
        ent[pos] = (uint16_t)(tid | (myE << 9) | (1 << 12));
    }
    __syncthreads();
    const int nslots = start[N_ETA];
    for (int s = tid; s < nslots; s += CHUNK) {
        if (ent[s] == 0) {
            int e = 0;
#pragma unroll
            for (int k = 1; k < N_ETA; k++) if (s >= start[k]) e = k;
            ent[s] = (uint16_t)(ent[start[e]] & 0x0FFF);   // valid=0
        }
    }
    __syncthreads();
    for (int s = tid; s < SLOTS; s += CHUNK) g_sorted[c * SLOTS + s] = ent[s];
}

// ---------------- packed f32x2 + smem/async helpers ----------------
__device__ __forceinline__ unsigned long long pack_ff(float x, float y) {
    unsigned long long r;
    asm("mov.b64 %0, {%1, %2};" : "=l"(r) : "f"(x), "f"(y));
    return r;
}
__device__ __forceinline__ void unpack_ff(float& x, float& y, unsigned long long v) {
    asm("mov.b64 {%0, %1}, %2;" : "=f"(x), "=f"(y) : "l"(v));
}
__device__ __forceinline__ void fma2(unsigned long long& acc, unsigned long long w, unsigned long long v) {
    asm("fma.rn.f32x2 %0, %1, %2, %0;" : "+l"(acc) : "l"(w), "l"(v));
}
__device__ __forceinline__ unsigned long long lds_u64(const float* p) {
    unsigned long long r;
    asm("ld.shared.u64 %0, [%1];" : "=l"(r) : "l"(__cvta_generic_to_shared(p)));
    return r;
}
__device__ __forceinline__ void lds_v4(float& a, float& b, float& c, float& d, const float* p) {
    asm("ld.shared.v4.f32 {%0, %1, %2, %3}, [%4];"
        : "=f"(a), "=f"(b), "=f"(c), "=f"(d) : "l"(__cvta_generic_to_shared(p)));
}
__device__ __forceinline__ float lds_f32(const float* p) {
    float r;
    asm("ld.shared.f32 %0, [%1];" : "=f"(r) : "l"(__cvta_generic_to_shared(p)));
    return r;
}
__device__ __forceinline__ void cp_async4(float* dst_smem, const float* src_gmem) {
    asm volatile("cp.async.ca.shared.global [%0], [%1], 4;"
                 :: "r"((uint32_t)__cvta_generic_to_shared(dst_smem)), "l"(src_gmem));
}
#define CP_COMMIT()  asm volatile("cp.async.commit_group;" ::: "memory")
#define CP_WAIT(n)   asm volatile("cp.async.wait_group %0;" :: "n"(n) : "memory")

// Per 512-px chunk: warp = one 32-slot slice; lane = team t2 (o in [17*t2,+17))
// x group g (4 same-expert pixels). W row loaded as 4x LDS.128 + 1 scalar into
// regs (independent batch), then 17 packs + 34 fma2. feat pre-permuted via
// cp.async 4B scatter so each group's 4 px are contiguous u64 pairs.
__global__ __launch_bounds__(THREADS, 1)
void compute_kernel(const float* __restrict__ feat, const float* __restrict__ W,
                    const float* __restrict__ b, float* __restrict__ out) {
    extern __shared__ float sh[];
    float* Wt   = sh;                          // 7 * WSTRIDE, layout [e][f][t2*20 + j]
    float* bs   = Wt + N_ETA * WSTRIDE;        // 480
    float* bufP = bs + 480;                    // 2 * TBUFW (permuted feat tiles)
    uint16_t* o2s = (uint16_t*)(bufP + 2 * TBUFW);   // 544

    const int tid = threadIdx.x;
    const int lane = tid & 31, warp = tid >> 5;
    const int g = lane & 7, t2 = lane >> 3;
    const int obase = t2 * 17;

    // stage W teamed: Wt[e*WSTRIDE + f*WROW + t2*20 + j] = W[e][17*t2+j][f]
    for (int i = tid; i < N_ETA * FDIM * FDIM; i += THREADS) {
        int e = i / (FDIM * FDIM);
        int rem = i - e * (FDIM * FDIM);
        int o = rem / FDIM;
        int f = rem - o * FDIM;
        int tt = o / 17, j = o - tt * 17;
        Wt[e * WSTRIDE + f * WROW + tt * 20 + j] = W[i];
    }
    for (int i = tid; i < N_ETA * FDIM; i += THREADS) bs[i] = b[i];
    __syncthreads();

    for (int c = blockIdx.x; c < NCH; c += gridDim.x) {
        const int cb = c * CHUNK;
        const int nsl = g_nsl[c];
        __syncthreads();                         // prior chunk fully consumed
        for (int s = tid; s < SLOTS; s += THREADS) {
            uint16_t en = g_sorted[c * SLOTS + s];
            if (en & (1 << 12)) o2s[en & 511] = (uint16_t)s;
        }
        __syncthreads();

        const bool active = (warp < nsl);
        unsigned long long ents = 0;
        if (active)
            ents = *(const unsigned long long*)(g_sorted + c * SLOTS + (warp << 5) + (g << 2));
        const int e = (int)((ents >> 9) & 7);
        const float* wbase = Wt + e * WSTRIDE + t2 * 20;
        const int slotbase = (warp << 5) + (g << 2);

        // acc[2j] = (px0,px1), acc[2j+1] = (px2,px3) for o = obase + j
        unsigned long long acc[34];
        if (active) {
            const float* bp = bs + e * FDIM + obase;
#pragma unroll
            for (int j = 0; j < 17; j++) {
                float bv = lds_f32(bp + j);
                unsigned long long bb = pack_ff(bv, bv);
                acc[2 * j] = bb;
                acc[2 * j + 1] = bb;
            }
        }

        // prologue: stage tile 0 permuted (coalesced gmem read, 4B smem scatter)
        for (int i = tid; i < 17 * CHUNK; i += THREADS) {   // exactly 16 iters
            int fl = i >> 9, px = i & 511;
            cp_async4(bufP + fl * SLOTS + o2s[px], feat + (size_t)fl * HW + cb + px);
        }
        CP_COMMIT();

        for (int t = 0; t < 4; t++) {
            if (t < 3) {
                const int f0 = (t + 1) * 17;
                float* dst = bufP + ((t + 1) & 1) * TBUFW;
                for (int i = tid; i < 17 * CHUNK; i += THREADS) {
                    int fl = i >> 9, px = i & 511;
                    cp_async4(dst + fl * SLOTS + o2s[px], feat + (size_t)(f0 + fl) * HW + cb + px);
                }
                CP_COMMIT();
                CP_WAIT(1);
            } else {
                CP_WAIT(0);
            }
            __syncthreads();
            if (active) {
                const float* B = bufP + (t & 1) * TBUFW + slotbase;
                const float* wrow = wbase + (t * 17) * WROW;
#pragma unroll 1
                for (int fl = 0; fl < 17; fl++) {
                    // batched, independent loads (all operands ready before math)
                    float w[17];
                    lds_v4(w[0],  w[1],  w[2],  w[3],  wrow);
                    lds_v4(w[4],  w[5],  w[6],  w[7],  wrow + 4);
                    lds_v4(w[8],  w[9],  w[10], w[11], wrow + 8);
                    lds_v4(w[12], w[13], w[14], w[15], wrow + 12);
                    w[16] = lds_f32(wrow + 16);
                    unsigned long long v01 = lds_u64(B + fl * SLOTS);
                    unsigned long long v23 = lds_u64(B + fl * SLOTS + 2);
#pragma unroll
                    for (int j = 0; j < 17; j++) {
                        unsigned long long ww = pack_ff(w[j], w[j]);
                        fma2(acc[2 * j],     ww, v01);
                        fma2(acc[2 * j + 1], ww, v23);
                    }
                    wrow += WROW;
                }
            }
            __syncthreads();
        }

        // epilogue: validity-masked scattered STG within the 2KB chunk window
        if (active) {
            const int l0 = (int)(ents & 511),          va0 = (int)((ents >> 12) & 1);
            const int l1 = (int)((ents >> 16) & 511),  va1 = (int)((ents >> 28) & 1);
            const int l2 = (int)((ents >> 32) & 511),  va2 = (int)((ents >> 44) & 1);
            const int l3 = (int)((ents >> 48) & 511),  va3 = (int)((ents >> 60) & 1);
            float* rowp = out + (size_t)obase * HW + cb;
#pragma unroll
            for (int j = 0; j < 17; j++) {
                float x, y;
                unpack_ff(x, y, acc[2 * j]);
                if (va0) rowp[l0] = x;
                if (va1) rowp[l1] = y;
                unpack_ff(x, y, acc[2 * j + 1]);
                if (va2) rowp[l2] = x;
                if (va3) rowp[l3] = y;
                rowp += HW;
            }
        }
    }
}

extern "C" void kernel_launch(void* const* d_in, const int* in_sizes, int n_in,
                              void* d_out, int out_size) {
    const float* x   = 0;   // 35,651,584
    const float* W   = 0;   // 32,368
    const float* b   = 0;   // 476
    const float* T   = 0;   // 49
    const int*   eta = 0;   // 524,288
    for (int i = 0; i < n_in; i++) {
        switch (in_sizes[i]) {
            case 35651584: x   = (const float*)d_in[i]; break;
            case 32368:    W   = (const float*)d_in[i]; break;
            case 476:      b   = (const float*)d_in[i]; break;
            case 49:       T   = (const float*)d_in[i]; break;
            case 524288:   eta = (const int*)d_in[i];   break;
        }
    }
    float* out = (float*)d_out;

    eta_sort_kernel<<<NCH, CHUNK>>>(T, eta);

    int smem = (N_ETA * WSTRIDE + 480 + 2 * TBUFW) * (int)sizeof(float)
             + SLOTS * (int)sizeof(uint16_t);          // 229,424 B
    cudaFuncSetAttribute(compute_kernel, cudaFuncAttributeMaxDynamicSharedMemorySize, smem);
    int dev = 0, sms = 148;
    cudaGetDevice(&dev);
    cudaDeviceGetAttribute(&sms, cudaDevAttrMultiProcessorCount, dev);
    compute_kernel<<<sms, THREADS, smem>>>(x, W, b, out);
}